// round 10
// baseline (speedup 1.0000x reference)
#include <cuda_runtime.h>
#include <cuda_fp16.h>
#include <cstdint>

// Winograd F(4x4,3x3): N=16, Cin=Cout=64, H=W=128, pad=1, nt=32, T=16384.
// Round 10: r8 pipeline + 2-chunk (8-image) scheduling so V/M stay L2-resident.
// Per chunk: V 37.7MB + M 37.7MB = 75.5MB < 126MB L2; the same scratch
// buffers are reused across chunks so dirty lines are overwritten in L2
// instead of written back to DRAM.
//
//   K0: weight (o,i,ab) fp32 -> g_Wh[ab][o][i] fp16
//   K1: input transform x(chunk) -> g_Vh[ab][i][tl] fp16 (tl local to chunk)
//   K2: HMMA: M[ab][o][tl] = sum_i W[o][i]*V[i][tl] (smem-staged row stores)
//   K3: output transform + bias -> y(chunk) fp32

#define CH 64
#define ABN 36
#define NCHUNK 2
#define NIMG 8                    // images per chunk
#define TQH (NIMG * 1024)         // 8192 tile-columns per chunk
#define VSLICE_H (CH * TQH)

__device__ __half g_Vh[ABN * CH * TQH];   // 37.7 MB (reused per chunk)
__device__ __half g_Mh[ABN * CH * TQH];   // 37.7 MB (reused per chunk)
__device__ __half g_Wh[ABN * CH * CH];

__device__ __forceinline__ uint32_t smem_u32(const void* p) {
    uint32_t a;
    asm("{ .reg .u64 t; cvta.to.shared.u64 t, %1; cvt.u32.u64 %0, t; }"
        : "=r"(a) : "l"(p));
    return a;
}

// ---------------------------------------------------------------------------
// K0: weight reorder. src w[o][i][ab] fp32 -> g_Wh[ab][o][i] fp16.
// ---------------------------------------------------------------------------
__global__ void k_wreorder(const float* __restrict__ w) {
    int tid = blockIdx.x * blockDim.x + threadIdx.x;
    if (tid >= ABN * CH * 32) return;
    int i2 = tid & 31;
    int o  = (tid >> 5) & 63;
    int ab = tid >> 11;
    float a0 = w[(o * 64 + i2 * 2) * ABN + ab];
    float a1 = w[(o * 64 + i2 * 2 + 1) * ABN + ab];
    *(__half2*)(g_Wh + ab * (CH * CH) + o * CH + i2 * 2) =
        __floats2half2_rn(a0, a1);
}

// ---------------------------------------------------------------------------
// K1: input transform for one chunk -> g_Vh[ab][c][tl],
// tl = nl*1024 + p*32 + q, nl in 0..7, global image n = n0 + nl.
// ---------------------------------------------------------------------------
__device__ __forceinline__ void bt_apply(const float d0, const float d1,
                                         const float d2, const float d3,
                                         const float d4, const float d5,
                                         float* out) {
    out[0] = 4.f * d0 - 5.f * d2 + d4;
    out[1] = -4.f * (d1 + d2) + d3 + d4;
    out[2] = 4.f * (d1 - d2) - d3 + d4;
    out[3] = -2.f * d1 - d2 + 2.f * d3 + d4;
    out[4] = 2.f * d1 - d2 - 2.f * d3 + d4;
    out[5] = 4.f * d1 - 5.f * d3 + d5;
}

__global__ __launch_bounds__(256)
void k_input_transform(const float* __restrict__ x, int n0) {
    int tid = blockIdx.x * blockDim.x + threadIdx.x;   // 524288 threads
    int q  = tid & 31;
    int p  = (tid >> 5) & 31;
    int c  = (tid >> 10) & 63;
    int nl = tid >> 16;                                // 0..7

    const float* xp = x + (((long)(n0 + nl) * CH + c) << 14);
    int r0 = p * 4 - 1;
    int c0 = q * 4 - 1;

    float d[6][6];
#pragma unroll
    for (int i = 0; i < 6; i++) {
        int r = r0 + i;
        bool rv = (r >= 0) && (r < 128);
        const float* row = xp + r * 128;
#pragma unroll
        for (int j = 0; j < 6; j++) {
            int cc = c0 + j;
            d[i][j] = (rv && cc >= 0 && cc < 128) ? row[cc] : 0.f;
        }
    }

    float wrow[6][6];
#pragma unroll
    for (int j = 0; j < 6; j++) {
        float t[6];
        bt_apply(d[0][j], d[1][j], d[2][j], d[3][j], d[4][j], d[5][j], t);
#pragma unroll
        for (int a = 0; a < 6; a++) wrow[a][j] = t[a];
    }

    int tl = (nl << 10) + (p << 5) + q;
    int base = c * TQH + tl;
#pragma unroll
    for (int a = 0; a < 6; a++) {
        float v[6];
        bt_apply(wrow[a][0], wrow[a][1], wrow[a][2], wrow[a][3], wrow[a][4],
                 wrow[a][5], v);
#pragma unroll
        for (int b = 0; b < 6; b++) {
            g_Vh[(a * 6 + b) * VSLICE_H + base] = __float2half_rn(v[b]);
        }
    }
}

// ---------------------------------------------------------------------------
// K2: HMMA GEMM. grid = (TQH/256 = 32, 36), block = 256 (8 warps).
// CTA tile: o=64, t=256, K=64 (resident). Warp tile 32(o) x 64(t).
// Epilogue: acc -> Ms (reuses Vs smem) -> full-row coalesced uint4 stores.
// ---------------------------------------------------------------------------
__global__ __launch_bounds__(256, 2)
void k_gemm_hmma() {
    __shared__ __half Ws[64][72];    // [o][i], +8 pad
    __shared__ __half Vs[64][264];   // [i][t], +8 pad; reused as Ms[64][264]

    const int tid = threadIdx.x;
    const int wid = tid >> 5;
    const int lid = tid & 31;
    const int ab = blockIdx.y;
    const int tb = blockIdx.x * 256;

    // Load W tile: 64x64 fp16 = 512 uint4.
    {
        const uint4* Wp = (const uint4*)(g_Wh + ab * (CH * CH));
#pragma unroll
        for (int it = 0; it < 2; it++) {
            int idx = tid + it * 256;
            int r = idx >> 3, c = idx & 7;
            *(uint4*)&Ws[r][c * 8] = Wp[idx];
        }
    }
    // Load V tile: 64 rows x 256 t fp16 = 2048 uint4.
    {
        const __half* Vp = g_Vh + ab * VSLICE_H + tb;
#pragma unroll
        for (int it = 0; it < 8; it++) {
            int idx = tid + it * 256;
            int r = idx >> 5, c = idx & 31;
            *(uint4*)&Vs[r][c * 8] =
                *(const uint4*)(Vp + (size_t)r * TQH + c * 8);
        }
    }
    __syncthreads();

    const int o0  = (wid & 1) * 32;
    const int t0w = (wid >> 1) * 64;

    float acc[2][8][4];
#pragma unroll
    for (int mi = 0; mi < 2; mi++)
#pragma unroll
        for (int nj = 0; nj < 8; nj++)
#pragma unroll
            for (int r = 0; r < 4; r++) acc[mi][nj][r] = 0.f;

#pragma unroll
    for (int ks = 0; ks < 4; ks++) {
        const int k0 = ks * 16;

        uint32_t ra[2][4];
#pragma unroll
        for (int mi = 0; mi < 2; mi++) {
            int row = o0 + mi * 16 + (lid & 7) + ((lid >> 3) & 1) * 8;
            int col = k0 + (lid >> 4) * 8;
            uint32_t addr = smem_u32(&Ws[row][col]);
            asm volatile(
                "ldmatrix.sync.aligned.m8n8.x4.shared.b16 {%0,%1,%2,%3}, [%4];"
                : "=r"(ra[mi][0]), "=r"(ra[mi][1]), "=r"(ra[mi][2]),
                  "=r"(ra[mi][3])
                : "r"(addr));
        }
        uint32_t rb[8][2];
#pragma unroll
        for (int njp = 0; njp < 4; njp++) {
            int row = k0 + (lid & 7) + ((lid >> 3) & 1) * 8;
            int col = t0w + njp * 16 + (lid >> 4) * 8;
            uint32_t addr = smem_u32(&Vs[row][col]);
            uint32_t r0, r1, r2, r3;
            asm volatile(
                "ldmatrix.sync.aligned.m8n8.x4.trans.shared.b16 {%0,%1,%2,%3}, [%4];"
                : "=r"(r0), "=r"(r1), "=r"(r2), "=r"(r3)
                : "r"(addr));
            rb[njp * 2][0] = r0; rb[njp * 2][1] = r1;
            rb[njp * 2 + 1][0] = r2; rb[njp * 2 + 1][1] = r3;
        }

#pragma unroll
        for (int mi = 0; mi < 2; mi++)
#pragma unroll
            for (int nj = 0; nj < 8; nj++) {
                asm volatile(
                    "mma.sync.aligned.m16n8k16.row.col.f32.f16.f16.f32 "
                    "{%0,%1,%2,%3}, {%4,%5,%6,%7}, {%8,%9}, {%0,%1,%2,%3};"
                    : "+f"(acc[mi][nj][0]), "+f"(acc[mi][nj][1]),
                      "+f"(acc[mi][nj][2]), "+f"(acc[mi][nj][3])
                    : "r"(ra[mi][0]), "r"(ra[mi][1]), "r"(ra[mi][2]),
                      "r"(ra[mi][3]), "r"(rb[nj][0]), "r"(rb[nj][1]));
            }
    }

    // All warps finished reading Vs -> reuse as Ms staging.
    __syncthreads();
    __half (*Ms)[264] = (__half (*)[264])Vs;

#pragma unroll
    for (int mi = 0; mi < 2; mi++) {
        int orow = o0 + mi * 16 + (lid >> 2);
#pragma unroll
        for (int nj = 0; nj < 8; nj++) {
            int tl = t0w + nj * 8 + (lid & 3) * 2;
            *(__half2*)&Ms[orow][tl] =
                __floats2half2_rn(acc[mi][nj][0], acc[mi][nj][1]);
            *(__half2*)&Ms[orow + 8][tl] =
                __floats2half2_rn(acc[mi][nj][2], acc[mi][nj][3]);
        }
    }
    __syncthreads();

    // Coalesced out: one warp per row, lane writes uint4 (8 halves).
    __half* Mp = g_Mh + ab * VSLICE_H + tb;
#pragma unroll
    for (int pass = 0; pass < 8; pass++) {
        int row = pass * 8 + wid;
        *(uint4*)(Mp + (size_t)row * TQH + lid * 8) =
            *(const uint4*)&Ms[row][lid * 8];
    }
}

// ---------------------------------------------------------------------------
// K3: output transform + bias for one chunk. 2 t per thread.
// ---------------------------------------------------------------------------
__global__ __launch_bounds__(256)
void k_output_transform(const float* __restrict__ bias,
                        float* __restrict__ y, int n0) {
    int tid = blockIdx.x * blockDim.x + threadIdx.x;   // 262144 threads
    int q2 = tid & 15;
    int p  = (tid >> 4) & 31;
    int o  = (tid >> 9) & 63;
    int nl = tid >> 15;                                // 0..7

    int tl = (nl << 10) + (p << 5) + (q2 << 1);
    int base = o * TQH + tl;

    float2 u[4][6];
#pragma unroll
    for (int b = 0; b < 6; b++) {
        float2 m[6];
#pragma unroll
        for (int a = 0; a < 6; a++)
            m[a] = __half22float2(
                *(const __half2*)(g_Mh + (a * 6 + b) * VSLICE_H + base));
        u[0][b].x = m[0].x + m[1].x + m[2].x + m[3].x + m[4].x;
        u[0][b].y = m[0].y + m[1].y + m[2].y + m[3].y + m[4].y;
        u[1][b].x = m[1].x - m[2].x + 2.f * (m[3].x - m[4].x);
        u[1][b].y = m[1].y - m[2].y + 2.f * (m[3].y - m[4].y);
        u[2][b].x = m[1].x + m[2].x + 4.f * (m[3].x + m[4].x);
        u[2][b].y = m[1].y + m[2].y + 4.f * (m[3].y + m[4].y);
        u[3][b].x = m[1].x - m[2].x + 8.f * (m[3].x - m[4].x) + m[5].x;
        u[3][b].y = m[1].y - m[2].y + 8.f * (m[3].y - m[4].y) + m[5].y;
    }

    float bv = bias[o];
    float* yp = y + (((size_t)(n0 + nl) * CH + o) << 14) + (p * 4) * 128
                + (q2 << 3);
#pragma unroll
    for (int xx = 0; xx < 4; xx++) {
        float2 m0 = u[xx][0], m1 = u[xx][1], m2 = u[xx][2];
        float2 m3 = u[xx][3], m4 = u[xx][4], m5 = u[xx][5];
        float4 v0, v1;
        v0.x = m0.x + m1.x + m2.x + m3.x + m4.x + bv;
        v0.y = m1.x - m2.x + 2.f * (m3.x - m4.x) + bv;
        v0.z = m1.x + m2.x + 4.f * (m3.x + m4.x) + bv;
        v0.w = m1.x - m2.x + 8.f * (m3.x - m4.x) + m5.x + bv;
        v1.x = m0.y + m1.y + m2.y + m3.y + m4.y + bv;
        v1.y = m1.y - m2.y + 2.f * (m3.y - m4.y) + bv;
        v1.z = m1.y + m2.y + 4.f * (m3.y + m4.y) + bv;
        v1.w = m1.y - m2.y + 8.f * (m3.y - m4.y) + m5.y + bv;
        *(float4*)(yp + xx * 128) = v0;
        *(float4*)(yp + xx * 128 + 4) = v1;
    }
}

// ---------------------------------------------------------------------------
extern "C" void kernel_launch(void* const* d_in, const int* in_sizes, int n_in,
                              void* d_out, int out_size) {
    const float* x    = (const float*)d_in[0];
    const float* w    = (const float*)d_in[1];
    const float* bias = (const float*)d_in[2];
    float* y = (float*)d_out;

    k_wreorder<<<(ABN * CH * 32 + 255) / 256, 256>>>(w);
    for (int ch = 0; ch < NCHUNK; ch++) {
        const int n0 = ch * NIMG;
        k_input_transform<<<2048, 256>>>(x, n0);
        dim3 g2(TQH / 256, ABN);
        k_gemm_hmma<<<g2, 256>>>();
        k_output_transform<<<1024, 256>>>(bias, y, n0);
    }
}

// round 11
// speedup vs baseline: 1.1294x; 1.1294x over previous
#include <cuda_runtime.h>
#include <cuda_fp16.h>
#include <cstdint>

// Winograd F(4x4,3x3): N=16, Cin=Cout=64, H=W=128, pad=1, nt=32, T=16384.
// Round 11: r8 pipeline with K2 rebuilt as a one-wave streaming GEMM:
// 288 CTAs (ab x 8 t-chunks), double-buffered cp.async V loads, W resident,
// coalesced smem-staged M stores.
//
//   K0: weight (o,i,ab) fp32 -> g_Wh[ab][o][i] fp16
//   K1: input transform x -> g_Vh[ab][i][t] fp16   (t = n*1024 + p*32 + q)
//   K2: HMMA: M[ab][o][t] = sum_i W[o][i] * V[i][t] -> g_Mh fp16
//   K3: output transform, 2 t per thread via half2, + bias -> y fp32

#define TQ 16384
#define CH 64
#define ABN 36
#define VSLICE (CH * TQ)

__device__ __half g_Vh[ABN * CH * TQ];   // 75.5 MB
__device__ __half g_Mh[ABN * CH * TQ];   // 75.5 MB
__device__ __half g_Wh[ABN * CH * CH];

__device__ __forceinline__ uint32_t smem_u32(const void* p) {
    uint32_t a;
    asm("{ .reg .u64 t; cvta.to.shared.u64 t, %1; cvt.u32.u64 %0, t; }"
        : "=r"(a) : "l"(p));
    return a;
}

#define CP_ASYNC16(dst, src) \
    asm volatile("cp.async.ca.shared.global [%0], [%1], 16;" \
                 :: "r"(dst), "l"(src) : "memory")
#define CP_COMMIT() asm volatile("cp.async.commit_group;" ::: "memory")
#define CP_WAIT1()  asm volatile("cp.async.wait_group 1;" ::: "memory")

// ---------------------------------------------------------------------------
// K0: weight reorder. src w[o][i][ab] fp32 -> g_Wh[ab][o][i] fp16.
// ---------------------------------------------------------------------------
__global__ void k_wreorder(const float* __restrict__ w) {
    int tid = blockIdx.x * blockDim.x + threadIdx.x;
    if (tid >= ABN * CH * 32) return;
    int i2 = tid & 31;
    int o  = (tid >> 5) & 63;
    int ab = tid >> 11;
    float a0 = w[(o * 64 + i2 * 2) * ABN + ab];
    float a1 = w[(o * 64 + i2 * 2 + 1) * ABN + ab];
    *(__half2*)(g_Wh + ab * (CH * CH) + o * CH + i2 * 2) =
        __floats2half2_rn(a0, a1);
}

// ---------------------------------------------------------------------------
// K1: input transform -> g_Vh[ab][c][t] fp16
// ---------------------------------------------------------------------------
__device__ __forceinline__ void bt_apply(const float d0, const float d1,
                                         const float d2, const float d3,
                                         const float d4, const float d5,
                                         float* out) {
    out[0] = 4.f * d0 - 5.f * d2 + d4;
    out[1] = -4.f * (d1 + d2) + d3 + d4;
    out[2] = 4.f * (d1 - d2) - d3 + d4;
    out[3] = -2.f * d1 - d2 + 2.f * d3 + d4;
    out[4] = 2.f * d1 - d2 - 2.f * d3 + d4;
    out[5] = 4.f * d1 - 5.f * d3 + d5;
}

__global__ __launch_bounds__(256)
void k_input_transform(const float* __restrict__ x) {
    int tid = blockIdx.x * blockDim.x + threadIdx.x;
    int q = tid & 31;
    int p = (tid >> 5) & 31;
    int c = (tid >> 10) & 63;
    int n = tid >> 16;

    const float* xp = x + (((long)n * CH + c) << 14);
    int r0 = p * 4 - 1;
    int c0 = q * 4 - 1;

    float d[6][6];
#pragma unroll
    for (int i = 0; i < 6; i++) {
        int r = r0 + i;
        bool rv = (r >= 0) && (r < 128);
        const float* row = xp + r * 128;
#pragma unroll
        for (int j = 0; j < 6; j++) {
            int cc = c0 + j;
            d[i][j] = (rv && cc >= 0 && cc < 128) ? row[cc] : 0.f;
        }
    }

    float wrow[6][6];
#pragma unroll
    for (int j = 0; j < 6; j++) {
        float t[6];
        bt_apply(d[0][j], d[1][j], d[2][j], d[3][j], d[4][j], d[5][j], t);
#pragma unroll
        for (int a = 0; a < 6; a++) wrow[a][j] = t[a];
    }

    int t = (n << 10) + (p << 5) + q;
    int base = c * TQ + t;
#pragma unroll
    for (int a = 0; a < 6; a++) {
        float v[6];
        bt_apply(wrow[a][0], wrow[a][1], wrow[a][2], wrow[a][3], wrow[a][4],
                 wrow[a][5], v);
#pragma unroll
        for (int b = 0; b < 6; b++) {
            g_Vh[(a * 6 + b) * VSLICE + base] = __float2half_rn(v[b]);
        }
    }
}

// ---------------------------------------------------------------------------
// K2: streaming HMMA GEMM. grid = (8, 36) = 288 CTAs (one wave @ 2/SM),
// block = 256 (8 warps). Each CTA: ab slice, 2048 t, 8 subtiles of 256 t.
// W (64x64) resident; V double-buffered via cp.async (prefetch distance 1,
// covered by a full compute+store iteration); M staged in the consumed V
// buffer then stored as full coalesced rows.
// Dynamic smem: Ws 9216 B + 2 x 33792 B = 76800 B.
// ---------------------------------------------------------------------------
#define K2_VS_OFF  9216
#define K2_VSTRIDE 33792
#define K2_SMEM    (K2_VS_OFF + 2 * K2_VSTRIDE)   // 76800

__global__ __launch_bounds__(256, 2)
void k_gemm_hmma() {
    extern __shared__ char sm[];
    __half (*Ws)[72] = (__half (*)[72])sm;          // [o][i], +8 pad

    const int tid = threadIdx.x;
    const int wid = tid >> 5;
    const int lid = tid & 31;
    const int ab = blockIdx.y;
    const int bx = blockIdx.x;
    const __half* Vbase = g_Vh + ab * VSLICE + bx * 2048;
    __half* Mbase = g_Mh + ab * VSLICE + bx * 2048;

    // Load W tile once: 64x64 fp16 = 512 uint4.
    {
        const uint4* Wp = (const uint4*)(g_Wh + ab * (CH * CH));
#pragma unroll
        for (int it = 0; it < 2; it++) {
            int idx = tid + it * 256;
            int r = idx >> 3, c = idx & 7;
            *(uint4*)&Ws[r][c * 8] = Wp[idx];
        }
    }

    // V prefetch: 64 rows x 256 t = 2048 uint4; thread does 8, row-coalesced.
    const int v_r = tid >> 5;          // base row group via idx>>5
    auto issueV = [&](int j, int buf) {
        const __half* Vp = Vbase + j * 256;
        char* dstb = sm + K2_VS_OFF + buf * K2_VSTRIDE;
#pragma unroll
        for (int it = 0; it < 8; it++) {
            int idx = tid + it * 256;
            int r = idx >> 5, c = idx & 31;
            CP_ASYNC16(smem_u32(dstb + r * 528 + c * 16),
                       Vp + (size_t)r * TQ + c * 8);
        }
    };

    issueV(0, 0);
    CP_COMMIT();

    const int o0  = (wid & 1) * 32;
    const int t0w = (wid >> 1) * 64;

#pragma unroll 1
    for (int j = 0; j < 8; j++) {
        // issue next prefetch (its buffer was fully consumed & stored at
        // iter j-1, ordered by the end-of-iter barrier).
        if (j + 1 < 8) issueV(j + 1, (j + 1) & 1);
        CP_COMMIT();
        CP_WAIT1();                    // group j complete
        __syncthreads();

        __half (*Vs)[264] =
            (__half (*)[264])(sm + K2_VS_OFF + (j & 1) * K2_VSTRIDE);

        float acc[2][8][4];
#pragma unroll
        for (int mi = 0; mi < 2; mi++)
#pragma unroll
            for (int nj = 0; nj < 8; nj++)
#pragma unroll
                for (int r = 0; r < 4; r++) acc[mi][nj][r] = 0.f;

#pragma unroll
        for (int ks = 0; ks < 4; ks++) {
            const int k0 = ks * 16;

            uint32_t ra[2][4];
#pragma unroll
            for (int mi = 0; mi < 2; mi++) {
                int row = o0 + mi * 16 + (lid & 7) + ((lid >> 3) & 1) * 8;
                int col = k0 + (lid >> 4) * 8;
                uint32_t addr = smem_u32(&Ws[row][col]);
                asm volatile(
                    "ldmatrix.sync.aligned.m8n8.x4.shared.b16 "
                    "{%0,%1,%2,%3}, [%4];"
                    : "=r"(ra[mi][0]), "=r"(ra[mi][1]), "=r"(ra[mi][2]),
                      "=r"(ra[mi][3])
                    : "r"(addr));
            }
            uint32_t rb[8][2];
#pragma unroll
            for (int njp = 0; njp < 4; njp++) {
                int row = k0 + (lid & 7) + ((lid >> 3) & 1) * 8;
                int col = t0w + njp * 16 + (lid >> 4) * 8;
                uint32_t addr = smem_u32(&Vs[row][col]);
                uint32_t r0, r1, r2, r3;
                asm volatile(
                    "ldmatrix.sync.aligned.m8n8.x4.trans.shared.b16 "
                    "{%0,%1,%2,%3}, [%4];"
                    : "=r"(r0), "=r"(r1), "=r"(r2), "=r"(r3)
                    : "r"(addr));
                rb[njp * 2][0] = r0; rb[njp * 2][1] = r1;
                rb[njp * 2 + 1][0] = r2; rb[njp * 2 + 1][1] = r3;
            }

#pragma unroll
            for (int mi = 0; mi < 2; mi++)
#pragma unroll
                for (int nj = 0; nj < 8; nj++) {
                    asm volatile(
                        "mma.sync.aligned.m16n8k16.row.col.f32.f16.f16.f32 "
                        "{%0,%1,%2,%3}, {%4,%5,%6,%7}, {%8,%9}, {%0,%1,%2,%3};"
                        : "+f"(acc[mi][nj][0]), "+f"(acc[mi][nj][1]),
                          "+f"(acc[mi][nj][2]), "+f"(acc[mi][nj][3])
                        : "r"(ra[mi][0]), "r"(ra[mi][1]), "r"(ra[mi][2]),
                          "r"(ra[mi][3]), "r"(rb[nj][0]), "r"(rb[nj][1]));
                }
        }

        // All warps done reading Vs -> reuse it as M staging.
        __syncthreads();
        __half (*Ms)[264] = Vs;

#pragma unroll
        for (int mi = 0; mi < 2; mi++) {
            int orow = o0 + mi * 16 + (lid >> 2);
#pragma unroll
            for (int nj = 0; nj < 8; nj++) {
                int tl = t0w + nj * 8 + (lid & 3) * 2;
                *(__half2*)&Ms[orow][tl] =
                    __floats2half2_rn(acc[mi][nj][0], acc[mi][nj][1]);
                *(__half2*)&Ms[orow + 8][tl] =
                    __floats2half2_rn(acc[mi][nj][2], acc[mi][nj][3]);
            }
        }
        __syncthreads();

        // Coalesced M stores: warp per row, lane = uint4 (8 halves).
        __half* Mp = Mbase + j * 256;
#pragma unroll
        for (int pass = 0; pass < 8; pass++) {
            int row = pass * 8 + wid;
            *(uint4*)(Mp + (size_t)row * TQ + lid * 8) =
                *(const uint4*)&Ms[row][lid * 8];
        }
        __syncthreads();   // LDS of staging done before next-iter prefetch
    }
    (void)v_r;
}

// ---------------------------------------------------------------------------
// K3: output transform + bias. 2 t per thread (half2 loads, float2 math).
// ---------------------------------------------------------------------------
__global__ __launch_bounds__(256)
void k_output_transform(const float* __restrict__ bias,
                        float* __restrict__ y) {
    int tid = blockIdx.x * blockDim.x + threadIdx.x;
    int q2 = tid & 15;
    int p  = (tid >> 4) & 31;
    int o  = (tid >> 9) & 63;
    int n  = tid >> 15;

    int t = (n << 10) + (p << 5) + (q2 << 1);
    int base = o * TQ + t;

    float2 u[4][6];
#pragma unroll
    for (int b = 0; b < 6; b++) {
        float2 m[6];
#pragma unroll
        for (int a = 0; a < 6; a++)
            m[a] = __half22float2(
                *(const __half2*)(g_Mh + (a * 6 + b) * VSLICE + base));
        u[0][b].x = m[0].x + m[1].x + m[2].x + m[3].x + m[4].x;
        u[0][b].y = m[0].y + m[1].y + m[2].y + m[3].y + m[4].y;
        u[1][b].x = m[1].x - m[2].x + 2.f * (m[3].x - m[4].x);
        u[1][b].y = m[1].y - m[2].y + 2.f * (m[3].y - m[4].y);
        u[2][b].x = m[1].x + m[2].x + 4.f * (m[3].x + m[4].x);
        u[2][b].y = m[1].y + m[2].y + 4.f * (m[3].y + m[4].y);
        u[3][b].x = m[1].x - m[2].x + 8.f * (m[3].x - m[4].x) + m[5].x;
        u[3][b].y = m[1].y - m[2].y + 8.f * (m[3].y - m[4].y) + m[5].y;
    }

    float bv = bias[o];
    float* yp = y + (((size_t)n * CH + o) << 14) + (p * 4) * 128 + (q2 << 3);
#pragma unroll
    for (int xx = 0; xx < 4; xx++) {
        float2 m0 = u[xx][0], m1 = u[xx][1], m2 = u[xx][2];
        float2 m3 = u[xx][3], m4 = u[xx][4], m5 = u[xx][5];
        float4 v0, v1;
        v0.x = m0.x + m1.x + m2.x + m3.x + m4.x + bv;
        v0.y = m1.x - m2.x + 2.f * (m3.x - m4.x) + bv;
        v0.z = m1.x + m2.x + 4.f * (m3.x + m4.x) + bv;
        v0.w = m1.x - m2.x + 8.f * (m3.x - m4.x) + m5.x + bv;
        v1.x = m0.y + m1.y + m2.y + m3.y + m4.y + bv;
        v1.y = m1.y - m2.y + 2.f * (m3.y - m4.y) + bv;
        v1.z = m1.y + m2.y + 4.f * (m3.y + m4.y) + bv;
        v1.w = m1.y - m2.y + 8.f * (m3.y - m4.y) + m5.y + bv;
        *(float4*)(yp + xx * 128) = v0;
        *(float4*)(yp + xx * 128 + 4) = v1;
    }
}

// ---------------------------------------------------------------------------
extern "C" void kernel_launch(void* const* d_in, const int* in_sizes, int n_in,
                              void* d_out, int out_size) {
    const float* x    = (const float*)d_in[0];
    const float* w    = (const float*)d_in[1];
    const float* bias = (const float*)d_in[2];
    float* y = (float*)d_out;

    cudaFuncSetAttribute(k_gemm_hmma,
                         cudaFuncAttributeMaxDynamicSharedMemorySize, K2_SMEM);

    k_wreorder<<<(ABN * CH * 32 + 255) / 256, 256>>>(w);
    k_input_transform<<<4096, 256>>>(x);
    dim3 g2(8, ABN);
    k_gemm_hmma<<<g2, 256, K2_SMEM>>>();
    k_output_transform<<<2048, 256>>>(bias, y);
}